// round 14
// baseline (speedup 1.0000x reference)
#include <cuda_runtime.h>
#include <cuda_bf16.h>
#include <cstdint>

#define BATCH 16
#define TLEN  2048
#define DIM   512
#define FDIM  256
#define QKV3  768
#define MTOT  (BATCH * TLEN)   // 32768

typedef __nv_bfloat16  bf16;
typedef __nv_bfloat162 bf162;

// ------------------------- scratch (__device__ globals) ---------------------
__device__ bf16 g_wqT[QKV3 * DIM];            // W_qkv^T bf16 [768,512]
__device__ bf16 g_woT[DIM * FDIM];            // W_out^T bf16 [512,256]
__device__ bf16 g_qkvb[(size_t)MTOT * QKV3];  // [M,768] q|k|v (q pre-scaled 1/16)

// ------------------------------ helpers -------------------------------------
__device__ __forceinline__ uint32_t smem_u32(const void* p) {
    uint32_t a;
    asm("{ .reg .u64 t; cvta.to.shared.u64 t, %1; cvt.u32.u64 %0, t; }" : "=r"(a) : "l"(p));
    return a;
}
#define CP_ASYNC16(dst, src) \
    asm volatile("cp.async.cg.shared.global [%0], [%1], 16;" :: "r"(dst), "l"(src))
#define CP_COMMIT() asm volatile("cp.async.commit_group;" ::: "memory")
#define LDSM_X4(r0, r1, r2, r3, addr) \
    asm volatile("ldmatrix.sync.aligned.m8n8.x4.shared.b16 {%0,%1,%2,%3}, [%4];" \
        : "=r"(r0), "=r"(r1), "=r"(r2), "=r"(r3) : "r"(addr))
#define LDSM_X4T(r0, r1, r2, r3, addr) \
    asm volatile("ldmatrix.sync.aligned.m8n8.x4.trans.shared.b16 {%0,%1,%2,%3}, [%4];" \
        : "=r"(r0), "=r"(r1), "=r"(r2), "=r"(r3) : "r"(addr))

__device__ __forceinline__ void mma16(float* c, const uint32_t* a, const uint32_t* b) {
    asm volatile(
        "mma.sync.aligned.m16n8k16.row.col.f32.bf16.bf16.f32 "
        "{%0,%1,%2,%3}, {%4,%5,%6,%7}, {%8,%9}, {%0,%1,%2,%3};"
        : "+f"(c[0]), "+f"(c[1]), "+f"(c[2]), "+f"(c[3])
        : "r"(a[0]), "r"(a[1]), "r"(a[2]), "r"(a[3]), "r"(b[0]), "r"(b[1]));
}

// ------------------------------ bf16 NT GEMM (QKV; round-13, proven) --------
#define SROW   72
#define ATILE  (128 * SROW * 2)
#define STAGE  (2 * ATILE)
#define SMEM_GEMM (2 * STAGE)

__global__ void __launch_bounds__(256, 2) qkv_gemm_kernel(
    const float* __restrict__ A, int lda,
    const bf16* __restrict__ B, int ldb,
    bf16* __restrict__ C, int ldc,
    const float* __restrict__ bias, int qcols, int K)
{
    extern __shared__ char smem[];
    const uint32_t sb = smem_u32(smem);
    const int tid  = threadIdx.x;
    const int lane = tid & 31;
    const int wid  = tid >> 5;
    const int wm   = (wid & 1) * 64;
    const int wn   = (wid >> 1) * 32;

    const float* Agf = A + (size_t)blockIdx.y * 128 * lda;
    const bf16*  Bg  = B + (size_t)blockIdx.x * 128 * ldb;

    const int NC = K >> 6;

    float4 aregs[8];
    auto ldgA = [&](int c) {
        const int k0 = c << 6;
        #pragma unroll
        for (int i = 0; i < 8; i++) {
            const int idx = tid + i * 256;
            const int r = idx >> 4, q = idx & 15;
            aregs[i] = *(const float4*)(Agf + (size_t)r * lda + k0 + q * 4);
        }
    };
    auto stsA = [&](int s) {
        #pragma unroll
        for (int i = 0; i < 8; i++) {
            const int idx = tid + i * 256;
            const int r = idx >> 4, q = idx & 15;
            bf16* p = (bf16*)(smem + s * STAGE + (uint32_t)(r * SROW + q * 4) * 2);
            *(bf162*)(p)     = __float22bfloat162_rn(make_float2(aregs[i].x, aregs[i].y));
            *(bf162*)(p + 2) = __float22bfloat162_rn(make_float2(aregs[i].z, aregs[i].w));
        }
    };
    auto loadB = [&](int c, int s) {
        const int k0 = c << 6;
        const uint32_t bb = sb + s * STAGE + ATILE;
        #pragma unroll
        for (int i = 0; i < 4; i++) {
            const int idx = tid + i * 256;
            const int r = idx >> 3, kq = idx & 7;
            CP_ASYNC16(bb + (uint32_t)(r * SROW + kq * 8) * 2,
                       Bg + (size_t)r * ldb + k0 + kq * 8);
        }
    };

    float acc[4][4][4];
    #pragma unroll
    for (int i = 0; i < 4; i++)
        #pragma unroll
        for (int j = 0; j < 4; j++)
            #pragma unroll
            for (int r = 0; r < 4; r++) acc[i][j][r] = 0.0f;

    ldgA(0); stsA(0);
    loadB(0, 0); CP_COMMIT();

    const uint32_t a_off =
        (uint32_t)((wm + (lane & 15)) * SROW + (lane >> 4) * 8) * 2;
    const uint32_t b_off =
        (uint32_t)((wn + (lane & 7) + ((lane >> 4) & 1) * 8) * SROW +
                   ((lane >> 3) & 1) * 8) * 2;

    for (int c = 0; c < NC; c++) {
        const int s = c & 1;
        if (c + 1 < NC) {
            ldgA(c + 1);
            loadB(c + 1, s ^ 1); CP_COMMIT();
            asm volatile("cp.async.wait_group 1;" ::: "memory");
        } else {
            asm volatile("cp.async.wait_group 0;" ::: "memory");
        }
        __syncthreads();

        const uint32_t abase = sb + s * STAGE + a_off;
        const uint32_t bbase = sb + s * STAGE + ATILE + b_off;

        #pragma unroll
        for (int kk = 0; kk < 4; kk++) {
            uint32_t a[4][4], b[2][4];
            #pragma unroll
            for (int mt = 0; mt < 4; mt++)
                LDSM_X4(a[mt][0], a[mt][1], a[mt][2], a[mt][3],
                        abase + mt * (16 * SROW * 2) + kk * 32);
            #pragma unroll
            for (int p = 0; p < 2; p++)
                LDSM_X4(b[p][0], b[p][1], b[p][2], b[p][3],
                        bbase + p * (16 * SROW * 2) + kk * 32);
            #pragma unroll
            for (int mt = 0; mt < 4; mt++)
                #pragma unroll
                for (int nt = 0; nt < 4; nt++)
                    mma16(acc[mt][nt], a[mt], &b[nt >> 1][(nt & 1) * 2]);
        }
        if (c + 1 < NC) stsA(s ^ 1);
        __syncthreads();
    }

    const int fr = lane >> 2;
    const int fc = lane & 3;
    const int gm = blockIdx.y * 128 + wm;
    const int gn = blockIdx.x * 128 + wn;

    #pragma unroll
    for (int mt = 0; mt < 4; mt++) {
        #pragma unroll
        for (int nt = 0; nt < 4; nt++) {
            const int col = gn + nt * 8 + fc * 2;
            const float2 bb = *(const float2*)(bias + col);
            const float f = (col < qcols) ? 0.0625f : 1.0f;
            #pragma unroll
            for (int h = 0; h < 2; h++) {
                const int row = gm + mt * 16 + fr + h * 8;
                const float v0 = (acc[mt][nt][2 * h + 0] + bb.x) * f;
                const float v1 = (acc[mt][nt][2 * h + 1] + bb.y) * f;
                *(bf162*)(C + (size_t)row * ldc + col) =
                    __float22bfloat162_rn(make_float2(v0, v1));
            }
        }
    }
}

// -------- flash attention (fixed-max) + fused output projection --------------
// Per CTA: 128 Q rows x 1 batch, BK=64, 512 thr (16 warps, 4M x 4N).
// After the KV loop, ctx is normalized into smem (reusing Q region) and the
// CTA runs out[128,512] = ctx @ W_out^T + b_out + residual over 8 double-
// buffered 64-col W chunks (reusing the K/V buffers), with the same proven
// fragment maps and prefetch/barrier schedule as the S phase / KV loop.
#define BK    64
#define QROW  264
#define PROW  72
#define OFF_K   67584
#define OFF_V   135168
#define OFF_P   202752
#define OFF_SUM 221184
#define SMEM_FLASH 223232
#define KVT   33792
#define NCH   8                   // 512 / 64 output-column chunks

__global__ void __launch_bounds__(512, 1) flash_kernel(
    const bf16* __restrict__ qkv, float* __restrict__ out,
    const bf16* __restrict__ woT, const float* __restrict__ b_out,
    const float* __restrict__ residual)
{
    extern __shared__ char smem[];
    const uint32_t sb = smem_u32(smem);
    bf16*  sP   = (bf16*)(smem + OFF_P);
    float* sSum = (float*)(smem + OFF_SUM);

    const int tid  = threadIdx.x;
    const int lane = tid & 31;
    const int wid  = tid >> 5;
    const int wm   = (wid & 3) * 32;
    const int wn   = wid >> 2;
    const int fr   = lane >> 2;
    const int fc   = lane & 3;
    const int t2   = lane >> 3;

    const int b  = blockIdx.y;
    const int q0 = blockIdx.x * 128;
    const bf16* qbase  = qkv + ((size_t)b * TLEN + q0) * QKV3;
    const bf16* kvbase = qkv + (size_t)b * TLEN * QKV3;

    #pragma unroll
    for (int i = 0; i < 8; i++) {
        const int idx = tid + i * 512;
        const int r = idx >> 5, c = (idx & 31) * 8;
        CP_ASYNC16(sb + (uint32_t)(r * QROW + c) * 2, qbase + (size_t)r * QKV3 + c);
    }
    auto loadKV = [&](int j, int s) {
        const bf16* kb = kvbase + (size_t)(j * BK) * QKV3 + FDIM;
        const bf16* vb = kvbase + (size_t)(j * BK) * QKV3 + 2 * FDIM;
        const uint32_t kd = sb + OFF_K + s * KVT;
        const uint32_t vd = sb + OFF_V + s * KVT;
        #pragma unroll
        for (int i = 0; i < 4; i++) {
            const int idx = tid + i * 512;
            const int r = idx >> 5, c = (idx & 31) * 8;
            CP_ASYNC16(kd + (uint32_t)(r * QROW + c) * 2, kb + (size_t)r * QKV3 + c);
        }
        #pragma unroll
        for (int i = 0; i < 4; i++) {
            const int idx = tid + i * 512;
            const int r = idx >> 5, c = (idx & 31) * 8;
            CP_ASYNC16(vd + (uint32_t)(r * QROW + c) * 2, vb + (size_t)r * QKV3 + c);
        }
    };
    loadKV(0, 0); CP_COMMIT();

    float acc_o[2][8][4];
    #pragma unroll
    for (int i = 0; i < 2; i++)
        #pragma unroll
        for (int j = 0; j < 8; j++)
            #pragma unroll
            for (int r = 0; r < 4; r++) acc_o[i][j][r] = 0.0f;

    float lpart[2][2] = {{0.0f, 0.0f}, {0.0f, 0.0f}};

    const uint32_t aq_off = (uint32_t)((wm + (lane & 15)) * QROW + (lane >> 4) * 8) * 2;
    const uint32_t bk_off = (uint32_t)((wn * 16 + (lane & 7) + ((lane >> 4) & 1) * 8) * QROW +
                                       ((lane >> 3) & 1) * 8) * 2;
    const uint32_t ap_off = (uint32_t)((wm + (lane & 15)) * PROW + (lane >> 4) * 8) * 2;

    for (int j = 0; j < TLEN / BK; j++) {
        const int s = j & 1;
        asm volatile("cp.async.wait_group 0;" ::: "memory");
        __syncthreads();

        if (j + 1 < TLEN / BK) { loadKV(j + 1, s ^ 1); CP_COMMIT(); }

        float acc_s[2][2][4];
        #pragma unroll
        for (int i = 0; i < 2; i++)
            #pragma unroll
            for (int n = 0; n < 2; n++)
                #pragma unroll
                for (int r = 0; r < 4; r++) acc_s[i][n][r] = 0.0f;

        const uint32_t kb = sb + OFF_K + s * KVT;
        #pragma unroll
        for (int kf = 0; kf < 16; kf++) {
            uint32_t a0[4], a1[4], bB[4];
            LDSM_X4(a0[0], a0[1], a0[2], a0[3], sb + aq_off + kf * 32);
            LDSM_X4(a1[0], a1[1], a1[2], a1[3], sb + aq_off + 16 * QROW * 2 + kf * 32);
            LDSM_X4(bB[0], bB[1], bB[2], bB[3], kb + bk_off + kf * 32);
            mma16(acc_s[0][0], a0, &bB[0]);
            mma16(acc_s[0][1], a0, &bB[2]);
            mma16(acc_s[1][0], a1, &bB[0]);
            mma16(acc_s[1][1], a1, &bB[2]);
        }

        #pragma unroll
        for (int mt = 0; mt < 2; mt++) {
            #pragma unroll
            for (int h = 0; h < 2; h++) {
                const int r = wm + mt * 16 + h * 8 + fr;
                const float p0 = __expf(acc_s[mt][0][2 * h + 0]);
                const float p1 = __expf(acc_s[mt][0][2 * h + 1]);
                const float p2 = __expf(acc_s[mt][1][2 * h + 0]);
                const float p3 = __expf(acc_s[mt][1][2 * h + 1]);

                bf16* pr = sP + r * PROW + wn * 16 + fc * 2;
                *(bf162*)(pr)     = __float22bfloat162_rn(make_float2(p0, p1));
                *(bf162*)(pr + 8) = __float22bfloat162_rn(make_float2(p2, p3));

                lpart[mt][h] += (p0 + p1) + (p2 + p3);
            }
        }
        __syncthreads();

        const uint32_t vb = sb + OFF_V + s * KVT;
        #pragma unroll
        for (int kf = 0; kf < 4; kf++) {
            uint32_t a0[4], a1[4];
            LDSM_X4(a0[0], a0[1], a0[2], a0[3], sb + OFF_P + ap_off + kf * 32);
            LDSM_X4(a1[0], a1[1], a1[2], a1[3], sb + OFF_P + ap_off + 16 * PROW * 2 + kf * 32);
            #pragma unroll
            for (int p = 0; p < 4; p++) {
                uint32_t v[4];
                const int krow = kf * 16 + (t2 & 1) * 8 + (lane & 7);
                const int ncol = wn * 64 + p * 16 + (t2 >> 1) * 8;
                LDSM_X4T(v[0], v[1], v[2], v[3],
                         vb + (uint32_t)(krow * QROW + ncol) * 2);
                mma16(acc_o[0][p * 2 + 0], a0, &v[0]);
                mma16(acc_o[0][p * 2 + 1], a0, &v[2]);
                mma16(acc_o[1][p * 2 + 0], a1, &v[0]);
                mma16(acc_o[1][p * 2 + 1], a1, &v[2]);
            }
        }
    }

    // ---- row-sum reduction ----
    __syncthreads();
    #pragma unroll
    for (int mt = 0; mt < 2; mt++)
        #pragma unroll
        for (int h = 0; h < 2; h++) {
            float lp = lpart[mt][h];
            lp += __shfl_xor_sync(~0u, lp, 1);
            lp += __shfl_xor_sync(~0u, lp, 2);
            if (fc == 0) sSum[(wm + mt * 16 + h * 8 + fr) * 4 + wn] = lp;
        }
    __syncthreads();

    // ---- normalize ctx into smem staging (reuse Q region, stride QROW) ----
    bf16* sCtx = (bf16*)smem;
    #pragma unroll
    for (int mt = 0; mt < 2; mt++) {
        #pragma unroll
        for (int h = 0; h < 2; h++) {
            const int r = wm + mt * 16 + h * 8 + fr;
            const float inv = 1.0f / (sSum[r * 4 + 0] + sSum[r * 4 + 1] +
                                      sSum[r * 4 + 2] + sSum[r * 4 + 3]);
            #pragma unroll
            for (int nt = 0; nt < 8; nt++) {
                const int col = wn * 64 + nt * 8 + fc * 2;
                *(bf162*)(sCtx + r * QROW + col) = __float22bfloat162_rn(
                    make_float2(acc_o[mt][nt][2 * h + 0] * inv,
                                acc_o[mt][nt][2 * h + 1] * inv));
            }
        }
    }

    // ---- fused out-proj: out[128,512] = ctx @ W_out^T + b_out + residual ----
    auto loadW = [&](int nc, int s) {
        const bf16* wb = woT + (size_t)(nc * 64) * FDIM;
        const uint32_t wd = sb + OFF_K + s * KVT;
        #pragma unroll
        for (int i = 0; i < 4; i++) {
            const int idx = tid + i * 512;
            const int r = idx >> 5, c = (idx & 31) * 8;
            CP_ASYNC16(wd + (uint32_t)(r * QROW + c) * 2, wb + (size_t)r * FDIM + c);
        }
    };
    loadW(0, 0); CP_COMMIT();

    const size_t grow0 = (size_t)b * TLEN + q0;

    for (int nc = 0; nc < NCH; nc++) {
        const int s = nc & 1;
        asm volatile("cp.async.wait_group 0;" ::: "memory");
        __syncthreads();   // chunk nc visible; staging visible (nc=0); prior reads of buf s^1 done

        if (nc + 1 < NCH) { loadW(nc + 1, s ^ 1); CP_COMMIT(); }

        float acc[2][2][4];
        #pragma unroll
        for (int i = 0; i < 2; i++)
            #pragma unroll
            for (int n = 0; n < 2; n++)
                #pragma unroll
                for (int r = 0; r < 4; r++) acc[i][n][r] = 0.0f;

        const uint32_t wbuf = sb + OFF_K + s * KVT;
        #pragma unroll
        for (int kf = 0; kf < 16; kf++) {
            uint32_t a0[4], a1[4], bB[4];
            LDSM_X4(a0[0], a0[1], a0[2], a0[3], sb + aq_off + kf * 32);
            LDSM_X4(a1[0], a1[1], a1[2], a1[3], sb + aq_off + 16 * QROW * 2 + kf * 32);
            LDSM_X4(bB[0], bB[1], bB[2], bB[3], wbuf + bk_off + kf * 32);
            mma16(acc[0][0], a0, &bB[0]);
            mma16(acc[0][1], a0, &bB[2]);
            mma16(acc[1][0], a1, &bB[0]);
            mma16(acc[1][1], a1, &bB[2]);
        }

        // epilogue: bias + residual + store fp32
        #pragma unroll
        for (int nt = 0; nt < 2; nt++) {
            const int col = nc * 64 + wn * 16 + nt * 8 + fc * 2;
            const float2 bb = *(const float2*)(b_out + col);
            #pragma unroll
            for (int mt = 0; mt < 2; mt++) {
                #pragma unroll
                for (int h = 0; h < 2; h++) {
                    const size_t row = grow0 + wm + mt * 16 + h * 8 + fr;
                    const float2 rr = *(const float2*)(residual + row * DIM + col);
                    float2 v;
                    v.x = acc[mt][nt][2 * h + 0] + bb.x + rr.x;
                    v.y = acc[mt][nt][2 * h + 1] + bb.y + rr.y;
                    *(float2*)(out + row * DIM + col) = v;
                }
            }
        }
    }
}

// --------------------------- prep: weight transposes only --------------------
#define PREP_WQ_BLOCKS 384
#define PREP_WO_BLOCKS 128

__global__ void __launch_bounds__(256) prep_kernel(
    const float* __restrict__ W_qkv, const float* __restrict__ W_out,
    bf16* __restrict__ wqT, bf16* __restrict__ woT)
{
    __shared__ float tile[32][33];
    const int bx  = blockIdx.x;
    const int tid = threadIdx.x;
    const int tx = tid & 31, ty = tid >> 5;
    const float* in; bf16* out; int ldin, ldout, c0, r0;
    if (bx < PREP_WQ_BLOCKS) {
        in = W_qkv; out = wqT; ldin = QKV3; ldout = DIM;
        c0 = (bx % (QKV3 / 32)) * 32; r0 = (bx / (QKV3 / 32)) * 32;
    } else {
        const int blk = bx - PREP_WQ_BLOCKS;
        in = W_out; out = woT; ldin = DIM; ldout = FDIM;
        c0 = (blk % (DIM / 32)) * 32; r0 = (blk / (DIM / 32)) * 32;
    }
    #pragma unroll
    for (int j = 0; j < 32; j += 8)
        tile[ty + j][tx] = in[(size_t)(r0 + ty + j) * ldin + c0 + tx];
    __syncthreads();
    #pragma unroll
    for (int j = 0; j < 32; j += 8)
        out[(size_t)(c0 + ty + j) * ldout + r0 + tx] = __float2bfloat16(tile[tx][ty + j]);
}

// -------------------------------- launch ------------------------------------
extern "C" void kernel_launch(void* const* d_in, const int* in_sizes, int n_in,
                              void* d_out, int out_size)
{
    const float* inputs = (const float*)d_in[0];
    const float* W_qkv  = (const float*)d_in[1];
    const float* b_qkv  = (const float*)d_in[2];
    const float* W_out  = (const float*)d_in[3];
    const float* b_out  = (const float*)d_in[4];
    float* out = (float*)d_out;

    bf16 *wqT, *woT, *qkvb;
    cudaGetSymbolAddress((void**)&wqT,  g_wqT);
    cudaGetSymbolAddress((void**)&woT,  g_woT);
    cudaGetSymbolAddress((void**)&qkvb, g_qkvb);

    cudaFuncSetAttribute(qkv_gemm_kernel,
                         cudaFuncAttributeMaxDynamicSharedMemorySize, SMEM_GEMM);
    cudaFuncSetAttribute(flash_kernel,
                         cudaFuncAttributeMaxDynamicSharedMemorySize, SMEM_FLASH);

    // 0) weight transposes
    prep_kernel<<<PREP_WQ_BLOCKS + PREP_WO_BLOCKS, 256>>>(W_qkv, W_out, wqT, woT);

    // 1) QKV = bf16(inputs @ W_qkv + b_qkv), q cols pre-scaled 1/16
    qkv_gemm_kernel<<<dim3(QKV3 / 128, MTOT / 128, 1), 256, SMEM_GEMM>>>(
        inputs, DIM, wqT, DIM, qkvb, QKV3, b_qkv, FDIM, DIM);

    // 2) fused attention + output projection + residual -> out (fp32)
    flash_kernel<<<dim3(TLEN / 128, BATCH), 512, SMEM_FLASH>>>(
        qkvb, out, woT, b_out, inputs);
}

// round 15
// speedup vs baseline: 1.0555x; 1.0555x over previous
#include <cuda_runtime.h>
#include <cuda_bf16.h>
#include <cstdint>

#define BATCH 16
#define TLEN  2048
#define DIM   512
#define FDIM  256
#define QKV3  768
#define MTOT  (BATCH * TLEN)   // 32768

typedef __nv_bfloat16  bf16;
typedef __nv_bfloat162 bf162;

// ------------------------- scratch (__device__ globals) ---------------------
__device__ bf16 g_wqT[QKV3 * DIM];            // W_qkv^T bf16 [768,512]
__device__ bf16 g_woT[DIM * FDIM];            // W_out^T bf16 [512,256]
__device__ bf16 g_qkvb[(size_t)MTOT * QKV3];  // [M,768] q|k|v (q pre-scaled by log2e/16)
__device__ bf16 g_ctxb[(size_t)MTOT * FDIM];  // [M,256] bf16

// ------------------------------ helpers -------------------------------------
__device__ __forceinline__ uint32_t smem_u32(const void* p) {
    uint32_t a;
    asm("{ .reg .u64 t; cvta.to.shared.u64 t, %1; cvt.u32.u64 %0, t; }" : "=r"(a) : "l"(p));
    return a;
}
#define CP_ASYNC16(dst, src) \
    asm volatile("cp.async.cg.shared.global [%0], [%1], 16;" :: "r"(dst), "l"(src))
#define CP_COMMIT() asm volatile("cp.async.commit_group;" ::: "memory")
#define LDSM_X4(r0, r1, r2, r3, addr) \
    asm volatile("ldmatrix.sync.aligned.m8n8.x4.shared.b16 {%0,%1,%2,%3}, [%4];" \
        : "=r"(r0), "=r"(r1), "=r"(r2), "=r"(r3) : "r"(addr))
#define LDSM_X4T(r0, r1, r2, r3, addr) \
    asm volatile("ldmatrix.sync.aligned.m8n8.x4.trans.shared.b16 {%0,%1,%2,%3}, [%4];" \
        : "=r"(r0), "=r"(r1), "=r"(r2), "=r"(r3) : "r"(addr))

__device__ __forceinline__ void mma16(float* c, const uint32_t* a, const uint32_t* b) {
    asm volatile(
        "mma.sync.aligned.m16n8k16.row.col.f32.bf16.bf16.f32 "
        "{%0,%1,%2,%3}, {%4,%5,%6,%7}, {%8,%9}, {%0,%1,%2,%3};"
        : "+f"(c[0]), "+f"(c[1]), "+f"(c[2]), "+f"(c[3])
        : "r"(a[0]), "r"(a[1]), "r"(a[2]), "r"(a[3]), "r"(b[0]), "r"(b[1]));
}

// q pre-scale: 1/16 (attention scale) * log2(e) (exp2 fold)
#define QSCALE 0.09016844f

// ------------------------------ bf16 NT GEMM --------------------------------
// AF32: A fp32 via LDG.128 (hidden under mma), converted+STS'd (STS.64) after
// mma, before the end barrier. OUT_BF16=false: staged coalesced fp32 epilogue.
#define SROW   72
#define ATILE  (128 * SROW * 2)
#define STAGE  (2 * ATILE)
#define SMEM_GEMM (2 * STAGE)

template<bool OUT_BF16, bool AF32>
__global__ void __launch_bounds__(256, 2) bf16_gemm_kernel(
    const void* __restrict__ Av, int lda, long long sA,
    const bf16* __restrict__ B, int ldb, long long sB,
    void* __restrict__ Cv, int ldc, long long sC,
    const float* __restrict__ bias, const float* __restrict__ residual,
    int qcols, int K)
{
    extern __shared__ char smem[];
    const uint32_t sb = smem_u32(smem);
    const int tid  = threadIdx.x;
    const int lane = tid & 31;
    const int wid  = tid >> 5;
    const int wm   = (wid & 1) * 64;
    const int wn   = (wid >> 1) * 32;

    const bf16*  Agb = (const bf16*)Av + blockIdx.z * sA + (size_t)blockIdx.y * 128 * lda;
    const float* Agf = (const float*)Av + blockIdx.z * sA + (size_t)blockIdx.y * 128 * lda;
    const bf16*  Bg  = B + blockIdx.z * sB + (size_t)blockIdx.x * 128 * ldb;

    const int NC = K >> 6;

    float4 aregs[8];
    auto ldgA = [&](int c) {
        const int k0 = c << 6;
        #pragma unroll
        for (int i = 0; i < 8; i++) {
            const int idx = tid + i * 256;
            const int r = idx >> 4, q = idx & 15;
            aregs[i] = *(const float4*)(Agf + (size_t)r * lda + k0 + q * 4);
        }
    };
    auto stsA = [&](int s) {
        #pragma unroll
        for (int i = 0; i < 8; i++) {
            const int idx = tid + i * 256;
            const int r = idx >> 4, q = idx & 15;
            uint2 pk;
            pk.x = ((uint32_t)__float22bfloat162_rn(make_float2(aregs[i].x, aregs[i].y)).y << 16) |
                   (uint16_t)__bfloat16_as_ushort(__float2bfloat16_rn(aregs[i].x));
            // build via union-free path: pack two bf162s
            bf162 lo = __float22bfloat162_rn(make_float2(aregs[i].x, aregs[i].y));
            bf162 hi = __float22bfloat162_rn(make_float2(aregs[i].z, aregs[i].w));
            pk.x = *(uint32_t*)&lo;
            pk.y = *(uint32_t*)&hi;
            *(uint2*)(smem + s * STAGE + (uint32_t)(r * SROW + q * 4) * 2) = pk;
        }
    };
    auto loadA_async = [&](int c, int s) {
        const int k0 = c << 6;
        const uint32_t ab = sb + s * STAGE;
        #pragma unroll
        for (int i = 0; i < 4; i++) {
            const int idx = tid + i * 256;
            const int r = idx >> 3, kq = idx & 7;
            CP_ASYNC16(ab + (uint32_t)(r * SROW + kq * 8) * 2,
                       Agb + (size_t)r * lda + k0 + kq * 8);
        }
    };
    auto loadB = [&](int c, int s) {
        const int k0 = c << 6;
        const uint32_t bb = sb + s * STAGE + ATILE;
        #pragma unroll
        for (int i = 0; i < 4; i++) {
            const int idx = tid + i * 256;
            const int r = idx >> 3, kq = idx & 7;
            CP_ASYNC16(bb + (uint32_t)(r * SROW + kq * 8) * 2,
                       Bg + (size_t)r * ldb + k0 + kq * 8);
        }
    };

    float acc[4][4][4];
    #pragma unroll
    for (int i = 0; i < 4; i++)
        #pragma unroll
        for (int j = 0; j < 4; j++)
            #pragma unroll
            for (int r = 0; r < 4; r++) acc[i][j][r] = 0.0f;

    if (AF32) { ldgA(0); stsA(0); }
    else      loadA_async(0, 0);
    loadB(0, 0); CP_COMMIT();

    const uint32_t a_off =
        (uint32_t)((wm + (lane & 15)) * SROW + (lane >> 4) * 8) * 2;
    const uint32_t b_off =
        (uint32_t)((wn + (lane & 7) + ((lane >> 4) & 1) * 8) * SROW +
                   ((lane >> 3) & 1) * 8) * 2;

    for (int c = 0; c < NC; c++) {
        const int s = c & 1;
        if (c + 1 < NC) {
            if (AF32) ldgA(c + 1);
            else      loadA_async(c + 1, s ^ 1);
            loadB(c + 1, s ^ 1); CP_COMMIT();
            asm volatile("cp.async.wait_group 1;" ::: "memory");
        } else {
            asm volatile("cp.async.wait_group 0;" ::: "memory");
        }
        __syncthreads();

        const uint32_t abase = sb + s * STAGE + a_off;
        const uint32_t bbase = sb + s * STAGE + ATILE + b_off;

        #pragma unroll
        for (int kk = 0; kk < 4; kk++) {
            uint32_t a[4][4], b[2][4];
            #pragma unroll
            for (int mt = 0; mt < 4; mt++)
                LDSM_X4(a[mt][0], a[mt][1], a[mt][2], a[mt][3],
                        abase + mt * (16 * SROW * 2) + kk * 32);
            #pragma unroll
            for (int p = 0; p < 2; p++)
                LDSM_X4(b[p][0], b[p][1], b[p][2], b[p][3],
                        bbase + p * (16 * SROW * 2) + kk * 32);
            #pragma unroll
            for (int mt = 0; mt < 4; mt++)
                #pragma unroll
                for (int nt = 0; nt < 4; nt++)
                    mma16(acc[mt][nt], a[mt], &b[nt >> 1][(nt & 1) * 2]);
        }
        if (AF32 && c + 1 < NC) stsA(s ^ 1);
        __syncthreads();
    }

    const int fr = lane >> 2;
    const int fc = lane & 3;
    const int gm = blockIdx.y * 128 + wm;
    const int gn = blockIdx.x * 128 + wn;
    const int bm = blockIdx.y * 128, bn = blockIdx.x * 128;

    if (OUT_BF16) {
        bf16* Cb = (bf16*)Cv + blockIdx.z * sC;
        #pragma unroll
        for (int mt = 0; mt < 4; mt++) {
            #pragma unroll
            for (int nt = 0; nt < 4; nt++) {
                const int col = gn + nt * 8 + fc * 2;
                float2 bb = make_float2(0.f, 0.f);
                if (bias) bb = *(const float2*)(bias + col);
                const float f = (col < qcols) ? QSCALE : 1.0f;
                #pragma unroll
                for (int h = 0; h < 2; h++) {
                    const int row = gm + mt * 16 + fr + h * 8;
                    const float v0 = (acc[mt][nt][2 * h + 0] + bb.x) * f;
                    const float v1 = (acc[mt][nt][2 * h + 1] + bb.y) * f;
                    *(bf162*)(Cb + (size_t)row * ldc + col) =
                        __float22bfloat162_rn(make_float2(v0, v1));
                }
            }
        }
    } else {
        float* st = (float*)smem;   // 128 x 132
        #pragma unroll
        for (int mt = 0; mt < 4; mt++)
            #pragma unroll
            for (int nt = 0; nt < 4; nt++)
                #pragma unroll
                for (int h = 0; h < 2; h++) {
                    const int row = wm + mt * 16 + fr + h * 8;
                    const int col = wn + nt * 8 + fc * 2;
                    st[row * 132 + col]     = acc[mt][nt][2 * h + 0];
                    st[row * 132 + col + 1] = acc[mt][nt][2 * h + 1];
                }
        __syncthreads();
        float* Cb = (float*)Cv + blockIdx.z * sC;
        #pragma unroll
        for (int i = 0; i < 16; i++) {
            const int idx = i * 256 + tid;
            const int r = idx >> 5, c4 = (idx & 31) * 4;
            float4 v = *(float4*)(st + r * 132 + c4);
            const int gc = bn + c4;
            const size_t gr = (size_t)(bm + r);
            if (bias) {
                const float4 b4 = *(const float4*)(bias + gc);
                v.x += b4.x; v.y += b4.y; v.z += b4.z; v.w += b4.w;
            }
            if (residual) {
                const float4 r4 = *(const float4*)(residual + gr * ldc + gc);
                v.x += r4.x; v.y += r4.y; v.z += r4.z; v.w += r4.w;
            }
            *(float4*)(Cb + gr * ldc + gc) = v;
        }
    }
}

// ------------------------------ flash attention (fixed-max) -------------------
// Per CTA: 128 Q rows x 1 batch, BK=64, 512 thr (16 warps, 4M x 4N).
// Q pre-scaled by log2e/16 -> p = exp2(s) directly. Row sums in regs, one
// final normalization. Race-free 2-barrier/iter schedule (round-12 proven).
#define BK    64
#define QROW  264
#define PROW  72
#define OFF_K   67584
#define OFF_V   135168
#define OFF_P   202752
#define OFF_SUM 221184
#define SMEM_FLASH 223232
#define KVT   33792

__global__ void __launch_bounds__(512, 1) flash_kernel(
    const bf16* __restrict__ qkv, bf16* __restrict__ ctx)
{
    extern __shared__ char smem[];
    const uint32_t sb = smem_u32(smem);
    bf16*  sP   = (bf16*)(smem + OFF_P);
    float* sSum = (float*)(smem + OFF_SUM);

    const int tid  = threadIdx.x;
    const int lane = tid & 31;
    const int wid  = tid >> 5;
    const int wm   = (wid & 3) * 32;
    const int wn   = wid >> 2;
    const int fr   = lane >> 2;
    const int fc   = lane & 3;
    const int t2   = lane >> 3;

    const int b  = blockIdx.y;
    const int q0 = blockIdx.x * 128;
    const bf16* qbase  = qkv + ((size_t)b * TLEN + q0) * QKV3;
    const bf16* kvbase = qkv + (size_t)b * TLEN * QKV3;

    #pragma unroll
    for (int i = 0; i < 8; i++) {
        const int idx = tid + i * 512;
        const int r = idx >> 5, c = (idx & 31) * 8;
        CP_ASYNC16(sb + (uint32_t)(r * QROW + c) * 2, qbase + (size_t)r * QKV3 + c);
    }
    auto loadKV = [&](int j, int s) {
        const bf16* kb = kvbase + (size_t)(j * BK) * QKV3 + FDIM;
        const bf16* vb = kvbase + (size_t)(j * BK) * QKV3 + 2 * FDIM;
        const uint32_t kd = sb + OFF_K + s * KVT;
        const uint32_t vd = sb + OFF_V + s * KVT;
        #pragma unroll
        for (int i = 0; i < 4; i++) {
            const int idx = tid + i * 512;
            const int r = idx >> 5, c = (idx & 31) * 8;
            CP_ASYNC16(kd + (uint32_t)(r * QROW + c) * 2, kb + (size_t)r * QKV3 + c);
        }
        #pragma unroll
        for (int i = 0; i < 4; i++) {
            const int idx = tid + i * 512;
            const int r = idx >> 5, c = (idx & 31) * 8;
            CP_ASYNC16(vd + (uint32_t)(r * QROW + c) * 2, vb + (size_t)r * QKV3 + c);
        }
    };
    loadKV(0, 0); CP_COMMIT();

    float acc_o[2][8][4];
    #pragma unroll
    for (int i = 0; i < 2; i++)
        #pragma unroll
        for (int j = 0; j < 8; j++)
            #pragma unroll
            for (int r = 0; r < 4; r++) acc_o[i][j][r] = 0.0f;

    float lpart[2][2] = {{0.0f, 0.0f}, {0.0f, 0.0f}};

    const uint32_t aq_off = (uint32_t)((wm + (lane & 15)) * QROW + (lane >> 4) * 8) * 2;
    const uint32_t bk_off = (uint32_t)((wn * 16 + (lane & 7) + ((lane >> 4) & 1) * 8) * QROW +
                                       ((lane >> 3) & 1) * 8) * 2;
    const uint32_t ap_off = (uint32_t)((wm + (lane & 15)) * PROW + (lane >> 4) * 8) * 2;

    for (int j = 0; j < TLEN / BK; j++) {
        const int s = j & 1;
        asm volatile("cp.async.wait_group 0;" ::: "memory");
        __syncthreads();   // tile j visible; prior-iter PV reads of buf s^1 done

        if (j + 1 < TLEN / BK) { loadKV(j + 1, s ^ 1); CP_COMMIT(); }

        float acc_s[2][2][4];
        #pragma unroll
        for (int i = 0; i < 2; i++)
            #pragma unroll
            for (int n = 0; n < 2; n++)
                #pragma unroll
                for (int r = 0; r < 4; r++) acc_s[i][n][r] = 0.0f;

        const uint32_t kb = sb + OFF_K + s * KVT;
        #pragma unroll
        for (int kf = 0; kf < 16; kf++) {
            uint32_t a0[4], a1[4], bB[4];
            LDSM_X4(a0[0], a0[1], a0[2], a0[3], sb + aq_off + kf * 32);
            LDSM_X4(a1[0], a1[1], a1[2], a1[3], sb + aq_off + 16 * QROW * 2 + kf * 32);
            LDSM_X4(bB[0], bB[1], bB[2], bB[3], kb + bk_off + kf * 32);
            mma16(acc_s[0][0], a0, &bB[0]);
            mma16(acc_s[0][1], a0, &bB[2]);
            mma16(acc_s[1][0], a1, &bB[0]);
            mma16(acc_s[1][1], a1, &bB[2]);
        }

        // ---- p = exp2(s) (log2e folded into Q pre-scale) ----
        #pragma unroll
        for (int mt = 0; mt < 2; mt++) {
            #pragma unroll
            for (int h = 0; h < 2; h++) {
                const int r = wm + mt * 16 + h * 8 + fr;
                const float p0 = exp2f(acc_s[mt][0][2 * h + 0]);
                const float p1 = exp2f(acc_s[mt][0][2 * h + 1]);
                const float p2 = exp2f(acc_s[mt][1][2 * h + 0]);
                const float p3 = exp2f(acc_s[mt][1][2 * h + 1]);

                bf16* pr = sP + r * PROW + wn * 16 + fc * 2;
                *(bf162*)(pr)     = __float22bfloat162_rn(make_float2(p0, p1));
                *(bf162*)(pr + 8) = __float22bfloat162_rn(make_float2(p2, p3));

                lpart[mt][h] += (p0 + p1) + (p2 + p3);
            }
        }
        __syncthreads();   // P visible before PV

        const uint32_t vb = sb + OFF_V + s * KVT;
        #pragma unroll
        for (int kf = 0; kf < 4; kf++) {
            uint32_t a0[4], a1[4];
            LDSM_X4(a0[0], a0[1], a0[2], a0[3], sb + OFF_P + ap_off + kf * 32);
            LDSM_X4(a1[0], a1[1], a1[2], a1[3], sb + OFF_P + ap_off + 16 * PROW * 2 + kf * 32);
            #pragma unroll
            for (int p = 0; p < 4; p++) {
                uint32_t v[4];
                const int krow = kf * 16 + (t2 & 1) * 8 + (lane & 7);
                const int ncol = wn * 64 + p * 16 + (t2 >> 1) * 8;
                LDSM_X4T(v[0], v[1], v[2], v[3],
                         vb + (uint32_t)(krow * QROW + ncol) * 2);
                mma16(acc_o[0][p * 2 + 0], a0, &v[0]);
                mma16(acc_o[0][p * 2 + 1], a0, &v[2]);
                mma16(acc_o[1][p * 2 + 0], a1, &v[0]);
                mma16(acc_o[1][p * 2 + 1], a1, &v[2]);
            }
        }
    }

    // ---- final row-sum reduction (sSum untouched during loop; shfl is
    //      warp-local, so no barrier needed before the writes) ----
    #pragma unroll
    for (int mt = 0; mt < 2; mt++)
        #pragma unroll
        for (int h = 0; h < 2; h++) {
            float lp = lpart[mt][h];
            lp += __shfl_xor_sync(~0u, lp, 1);
            lp += __shfl_xor_sync(~0u, lp, 2);
            if (fc == 0) sSum[(wm + mt * 16 + h * 8 + fr) * 4 + wn] = lp;
        }
    __syncthreads();

    #pragma unroll
    for (int mt = 0; mt < 2; mt++) {
        #pragma unroll
        for (int h = 0; h < 2; h++) {
            const int r = wm + mt * 16 + h * 8 + fr;
            const float inv = 1.0f / (sSum[r * 4 + 0] + sSum[r * 4 + 1] +
                                      sSum[r * 4 + 2] + sSum[r * 4 + 3]);
            bf16* orow = ctx + ((size_t)b * TLEN + q0 + r) * FDIM;
            #pragma unroll
            for (int nt = 0; nt < 8; nt++) {
                const int col = wn * 64 + nt * 8 + fc * 2;
                *(bf162*)(orow + col) = __float22bfloat162_rn(
                    make_float2(acc_o[mt][nt][2 * h + 0] * inv,
                                acc_o[mt][nt][2 * h + 1] * inv));
            }
        }
    }
}

// --------------------------- prep: weight transposes only --------------------
#define PREP_WQ_BLOCKS 384
#define PREP_WO_BLOCKS 128

__global__ void __launch_bounds__(256) prep_kernel(
    const float* __restrict__ W_qkv, const float* __restrict__ W_out,
    bf16* __restrict__ wqT, bf16* __restrict__ woT)
{
    __shared__ float tile[32][33];
    const int bx  = blockIdx.x;
    const int tid = threadIdx.x;
    const int tx = tid & 31, ty = tid >> 5;
    const float* in; bf16* out; int ldin, ldout, c0, r0;
    if (bx < PREP_WQ_BLOCKS) {
        in = W_qkv; out = wqT; ldin = QKV3; ldout = DIM;
        c0 = (bx % (QKV3 / 32)) * 32; r0 = (bx / (QKV3 / 32)) * 32;
    } else {
        const int blk = bx - PREP_WQ_BLOCKS;
        in = W_out; out = woT; ldin = DIM; ldout = FDIM;
        c0 = (blk % (DIM / 32)) * 32; r0 = (blk / (DIM / 32)) * 32;
    }
    #pragma unroll
    for (int j = 0; j < 32; j += 8)
        tile[ty + j][tx] = in[(size_t)(r0 + ty + j) * ldin + c0 + tx];
    __syncthreads();
    #pragma unroll
    for (int j = 0; j < 32; j += 8)
        out[(size_t)(c0 + ty + j) * ldout + r0 + tx] = __float2bfloat16(tile[tx][ty + j]);
}

// -------------------------------- launch ------------------------------------
extern "C" void kernel_launch(void* const* d_in, const int* in_sizes, int n_in,
                              void* d_out, int out_size)
{
    const float* inputs = (const float*)d_in[0];
    const float* W_qkv  = (const float*)d_in[1];
    const float* b_qkv  = (const float*)d_in[2];
    const float* W_out  = (const float*)d_in[3];
    const float* b_out  = (const float*)d_in[4];
    float* out = (float*)d_out;

    bf16 *wqT, *woT, *qkvb, *ctxb;
    cudaGetSymbolAddress((void**)&wqT,  g_wqT);
    cudaGetSymbolAddress((void**)&woT,  g_woT);
    cudaGetSymbolAddress((void**)&qkvb, g_qkvb);
    cudaGetSymbolAddress((void**)&ctxb, g_ctxb);

    cudaFuncSetAttribute((const void*)bf16_gemm_kernel<true, true>,
                         cudaFuncAttributeMaxDynamicSharedMemorySize, SMEM_GEMM);
    cudaFuncSetAttribute((const void*)bf16_gemm_kernel<false, false>,
                         cudaFuncAttributeMaxDynamicSharedMemorySize, SMEM_GEMM);
    cudaFuncSetAttribute((const void*)flash_kernel,
                         cudaFuncAttributeMaxDynamicSharedMemorySize, SMEM_FLASH);

    // 0) weight transposes
    prep_kernel<<<PREP_WQ_BLOCKS + PREP_WO_BLOCKS, 256>>>(W_qkv, W_out, wqT, woT);

    // 1) QKV = bf16(inputs @ W_qkv + b_qkv); q cols pre-scaled by log2e/16
    bf16_gemm_kernel<true, true><<<dim3(QKV3 / 128, MTOT / 128, 1), 256, SMEM_GEMM>>>(
        inputs, DIM, 0, wqT, DIM, 0, qkvb, QKV3, 0, b_qkv, nullptr, FDIM, DIM);

    // 2) fused attention -> ctx (bf16)
    flash_kernel<<<dim3(TLEN / 128, BATCH), 512, SMEM_FLASH>>>(qkvb, ctxb);

    // 3) out = inputs + ctx @ W_out + b_out (fp32, staged coalesced epilogue)
    bf16_gemm_kernel<false, false><<<dim3(DIM / 128, MTOT / 128, 1), 256, SMEM_GEMM>>>(
        ctxb, FDIM, 0, woT, FDIM, 0, out, DIM, 0, b_out, inputs, 0, FDIM);
}